// round 14
// baseline (speedup 1.0000x reference)
#include <cuda_runtime.h>
#include <cuda_bf16.h>
#include <cstdint>

#define T_STEPS 512
#define BATCH   512
#define INSZ    300
#define HID     16
#define NG      64
#define NROWS   (T_STEPS*BATCH)     // 262144
#define TILE_M  64
#define NTILES  (NROWS/TILE_M)      // 4096
#define GEMM_BLKS 296               // 2 per SM
#define SCAN_BLKS 128               // 1 per SM (mostly)
#define STRIDE_T (BATCH*NG)
#define ASTRIDE 56                  // 48 data cols + 8 pad (conflict-free LDS.64)

#define A_ELEMS (TILE_M*ASTRIDE)    // 3584 floats per buffer
#define B_WORDS (19*64*8)           // 9728 uint32
#define SMEM_BYTES (2*A_ELEMS*4 + B_WORDS*4)   // 28672*2? -> 28,672 + 38,912 = 67,584

__device__ float d_xg[(size_t)(NROWS + 8 * BATCH) * NG];
__device__ unsigned int d_flag[NTILES];

// ---------------- asm helpers ----------------
__device__ __forceinline__ uint32_t smem_u32(const void* p) {
    uint32_t a;
    asm("{ .reg .u64 t; cvta.to.shared.u64 t, %1; cvt.u32.u64 %0, t; }" : "=r"(a) : "l"(p));
    return a;
}
__device__ __forceinline__ void cp16(uint32_t sa, const float* g) {
    asm volatile("cp.async.cg.shared.global [%0], [%1], 16;" :: "r"(sa), "l"(g) : "memory");
}
#define CP_COMMIT() asm volatile("cp.async.commit_group;" ::: "memory")
#define CP_WAIT1()  asm volatile("cp.async.wait_group 1;" ::: "memory")

__device__ __forceinline__ void mma16816(float* d, uint32_t a0, uint32_t a1, uint32_t a2,
                                         uint32_t a3, uint32_t b0, uint32_t b1) {
    asm volatile(
        "mma.sync.aligned.m16n8k16.row.col.f32.bf16.bf16.f32 "
        "{%0,%1,%2,%3}, {%4,%5,%6,%7}, {%8,%9}, {%0,%1,%2,%3};"
        : "+f"(d[0]), "+f"(d[1]), "+f"(d[2]), "+f"(d[3])
        : "r"(a0), "r"(a1), "r"(a2), "r"(a3), "r"(b0), "r"(b1));
}
__device__ __forceinline__ uint32_t packbf(float lo, float hi) {
    __nv_bfloat162 p = __floats2bfloat162_rn(lo, hi);
    return *reinterpret_cast<uint32_t*>(&p);
}
__device__ __forceinline__ float tanhapx(float x) {
    float y;
    asm("tanh.approx.f32 %0, %1;" : "=f"(y) : "f"(x));
    return y;
}
__device__ __forceinline__ float sigt(float x) {
    return fmaf(tanhapx(0.5f * x), 0.5f, 0.5f);
}
__device__ __forceinline__ float sigx(float x) {
    float e = __expf(-x);
    return __fdividef(1.0f, 1.0f + e);
}
__device__ __forceinline__ unsigned ldacq(const unsigned* p) {
    unsigned v;
    asm volatile("ld.acquire.gpu.global.b32 %0, [%1];" : "=r"(v) : "l"(p) : "memory");
    return v;
}
// wait until steps t0..t0+3 for this side are produced (flag == 4)
__device__ __forceinline__ void wait4(int t0, int side) {
#pragma unroll
    for (int q = 0; q < 4; q++) {
        int t = t0 + q;
        if (t < T_STEPS) {
            const unsigned* f = &d_flag[8 * t + side];
            if (ldacq(f) != 4u)
                while (ldacq(f) != 4u) __nanosleep(128);
        }
    }
}

__global__ void zero_flags() {
    int i = blockIdx.x * 256 + threadIdx.x;
    if (i < NTILES) d_flag[i] = 0u;
}

// copy one K-chunk of a 64-row tile (128 threads). ch<6: 48 cols; ch==6: 12 cols + 4 zero
__device__ __forceinline__ void cp_chunk(const float* __restrict__ x, uint32_t abase,
                                         int tile, int ch) {
    const int tid = threadIdx.x;
    if (ch < 6) {
        const int c0 = ch * 48;
#pragma unroll
        for (int p = 0; p < 6; p++) {
            int idx = p * 128 + tid;
            int r = idx / 12, j = idx - r * 12;
            cp16(abase + ((uint32_t)(r * ASTRIDE) + 4u * (uint32_t)j) * 4u,
                 x + (size_t)(tile * TILE_M + r) * INSZ + c0 + 4 * j);
        }
    } else {
#pragma unroll
        for (int p = 0; p < 2; p++) {
            int idx = p * 128 + tid;
            int r = idx >> 2, j = idx & 3;
            uint32_t soff = abase + ((uint32_t)(r * ASTRIDE) + 4u * (uint32_t)j) * 4u;
            if (j < 3) {
                cp16(soff, x + (size_t)(tile * TILE_M + r) * INSZ + 288 + 4 * j);
            } else {
                asm volatile("st.shared.v4.u32 [%0], {%1,%1,%1,%1};" :: "r"(soff), "r"(0u) : "memory");
            }
        }
    }
    CP_COMMIT();
}

// ---------------- fused: 296 GEMM blocks + 128 scan blocks, all 128 threads ----------------
__global__ void __launch_bounds__(128, 3)
fused_kernel(const float* __restrict__ x, const float* __restrict__ W,
             const float* __restrict__ Whh,
             const float* __restrict__ b_ih, const float* __restrict__ b_hh,
             const float* __restrict__ W1, const float* __restrict__ b1,
             const float* __restrict__ W2, const float* __restrict__ b2,
             float* __restrict__ out) {
    extern __shared__ float sm[];
    const int tid  = threadIdx.x;
    const int lane = tid & 31;
    const unsigned FULL = 0xffffffffu;

    if (blockIdx.x < GEMM_BLKS) {
        // ================= GEMM block (bf16 mma, cp.async double-buffer) =================
        float* sA0 = sm;
        float* sA1 = sm + A_ELEMS;
        uint32_t* sB = reinterpret_cast<uint32_t*>(sm + 2 * A_ELEMS);
        const uint32_t sbase = smem_u32(sm);
        const uint32_t aB[2] = { sbase, sbase + A_ELEMS * 4u };
        float* sAp[2] = { sA0, sA1 };

        const int w  = tid >> 5;      // 0..3 -> rows w*16..w*16+15
        const int g  = lane >> 2;
        const int tg = lane & 3;

        cp_chunk(x, aB[0], blockIdx.x, 0);

        // B fill (once): W[n][k] fp32 -> bf16x2 fragment-pair layout
        for (int i = tid; i < 19 * 64 * 4; i += 128) {
            int s = i >> 8;
            int n = (i >> 2) & 63;
            int t = i & 3;
            int k0 = 16 * s + 2 * t;
            const float* Wn = W + (size_t)n * INSZ;
            float v0 = (k0     < INSZ) ? Wn[k0]     : 0.0f;
            float v1 = (k0 + 1 < INSZ) ? Wn[k0 + 1] : 0.0f;
            float v2 = (k0 + 8 < INSZ) ? Wn[k0 + 8] : 0.0f;
            float v3 = (k0 + 9 < INSZ) ? Wn[k0 + 9] : 0.0f;
            int base = ((s * 64 + n) * 4 + t) * 2;
            sB[base]     = packbf(v0, v1);
            sB[base + 1] = packbf(v2, v3);
        }
        __syncthreads();

        int buf = 0;
        for (int tile = blockIdx.x; tile < NTILES; tile += GEMM_BLKS) {
            float acc[8][4];
#pragma unroll
            for (int j = 0; j < 8; j++)
#pragma unroll
                for (int r = 0; r < 4; r++) acc[j][r] = 0.0f;

            for (int ch = 0; ch < 7; ch++) {
                int ntile = tile, nch = ch + 1;
                if (nch == 7) { ntile = tile + GEMM_BLKS; nch = 0; }
                if (ntile < NTILES) cp_chunk(x, aB[buf ^ 1], ntile, nch);
                else CP_COMMIT();
                CP_WAIT1();
                __syncthreads();

                const float* A = sAp[buf];
                const int nsl = (ch == 6) ? 1 : 3;
                for (int sl = 0; sl < nsl; sl++) {
                    const int s = ch * 3 + sl;   // global k16 step 0..18
                    uint2 bb[8];
                    const uint2* Bf = reinterpret_cast<const uint2*>(sB)
                                    + ((s * 64 + g) * 4 + tg);
#pragma unroll
                    for (int j = 0; j < 8; j++) bb[j] = Bf[j * 32];

                    const float* Ab = A + (w * 16 + g) * ASTRIDE + sl * 16 + 2 * tg;
                    float2 f0 = *reinterpret_cast<const float2*>(Ab);
                    float2 f1 = *reinterpret_cast<const float2*>(Ab + 8 * ASTRIDE);
                    float2 f2 = *reinterpret_cast<const float2*>(Ab + 8);
                    float2 f3 = *reinterpret_cast<const float2*>(Ab + 8 * ASTRIDE + 8);
                    uint32_t a0 = packbf(f0.x, f0.y);
                    uint32_t a1 = packbf(f1.x, f1.y);
                    uint32_t a2 = packbf(f2.x, f2.y);
                    uint32_t a3 = packbf(f3.x, f3.y);
#pragma unroll
                    for (int j = 0; j < 8; j++)
                        mma16816(acc[j], a0, a1, a2, a3, bb[j].x, bb[j].y);
                }
                __syncthreads();
                buf ^= 1;
            }

            // epilogue + publish
            {
                int r0 = tile * TILE_M + w * 16 + g;
#pragma unroll
                for (int j = 0; j < 8; j++) {
                    int col = j * 8 + tg * 2;
                    *reinterpret_cast<float2*>(&d_xg[(size_t)r0 * NG + col]) =
                        make_float2(acc[j][0], acc[j][1]);
                    *reinterpret_cast<float2*>(&d_xg[(size_t)(r0 + 8) * NG + col]) =
                        make_float2(acc[j][2], acc[j][3]);
                }
            }
            __threadfence();
            __syncwarp();
            if (lane == 0) atomicAdd(&d_flag[tile], 1u);
        }
    } else {
        // ================= scan block (R8 scan + flag gating) =================
        const int warp = tid >> 5;
        const int b = (blockIdx.x - GEMM_BLKS) * 4 + warp;
        const int l = lane & 15;
        const int side = b >> 6;           // 0..7 (64-row tiles)

        float w1r[HID], w2r[HID];
#pragma unroll
        for (int k = 0; k < HID; k++) {
            w1r[k] = Whh[lane * HID + k];
            w2r[k] = Whh[(lane + 32) * HID + k];
        }
        const float biasA = b_ih[lane] + b_hh[lane];
        const float biasB = b_ih[lane + 32] + b_hh[lane + 32];

        float h = 0.0f, c = 0.0f;
        const float* xpA = d_xg + (size_t)b * NG + lane;
        const float* xpB = xpA + 32;

        wait4(0, side);
        wait4(4, side);
        float xa0 = xpA[0 * STRIDE_T], xb0 = xpB[0 * STRIDE_T];
        float xa1 = xpA[1 * STRIDE_T], xb1 = xpB[1 * STRIDE_T];
        float xa2 = xpA[2 * STRIDE_T], xb2 = xpB[2 * STRIDE_T];
        float xa3 = xpA[3 * STRIDE_T], xb3 = xpB[3 * STRIDE_T];

#define STEP(XA, XB, PIDX)                                              \
    {                                                                   \
        float g1 = XA + biasA;                                          \
        float g2 = XB + biasB;                                          \
        XA = xpA[(size_t)(PIDX) * STRIDE_T];                            \
        XB = xpB[(size_t)(PIDX) * STRIDE_T];                            \
        float hk[HID];                                                  \
        _Pragma("unroll")                                               \
        for (int k = 0; k < HID; k++) hk[k] = __shfl_sync(FULL, h, k);  \
        float s0 = g1, s1 = 0.0f, s2 = 0.0f, s3 = 0.0f;                 \
        float r0 = g2, r1 = 0.0f, r2 = 0.0f, r3 = 0.0f;                 \
        _Pragma("unroll")                                               \
        for (int k = 0; k < HID; k += 4) {                              \
            s0 = fmaf(hk[k],     w1r[k],     s0);                       \
            s1 = fmaf(hk[k + 1], w1r[k + 1], s1);                       \
            s2 = fmaf(hk[k + 2], w1r[k + 2], s2);                       \
            s3 = fmaf(hk[k + 3], w1r[k + 3], s3);                       \
            r0 = fmaf(hk[k],     w2r[k],     r0);                       \
            r1 = fmaf(hk[k + 1], w2r[k + 1], r1);                       \
            r2 = fmaf(hk[k + 2], w2r[k + 2], r2);                       \
            r3 = fmaf(hk[k + 3], w2r[k + 3], r3);                       \
        }                                                               \
        g1 = (s0 + s1) + (s2 + s3);                                     \
        g2 = (r0 + r1) + (r2 + r3);                                     \
        float fg = __shfl_sync(FULL, g1, l + 16);                       \
        float og = __shfl_sync(FULL, g2, l + 16);                       \
        float i_s = sigt(g1);                                           \
        float f_s = sigt(fg);                                           \
        float g_t = tanhapx(g2);                                        \
        c = fmaf(f_s, c, i_s * g_t);                                    \
        h = sigt(og) * tanhapx(c);                                      \
    }

        for (int t = 0; t < T_STEPS; t += 4) {
            const int p = t + 4;
            STEP(xa0, xb0, p + 0)
            STEP(xa1, xb1, p + 1)
            STEP(xa2, xb2, p + 2)
            STEP(xa3, xb3, p + 3)
            if (t + 8 < T_STEPS) wait4(t + 8, side);
        }
#undef STEP

        float hk[HID];
#pragma unroll
        for (int k = 0; k < HID; k++) hk[k] = __shfl_sync(FULL, h, k);

        float wa[HID], wb[HID];
#pragma unroll
        for (int k = 0; k < HID; k++) {
            wa[k] = W1[lane * HID + k];
            wb[k] = W1[(lane + 32) * HID + k];
        }
        float za = b1[lane], zb = b1[lane + 32];
#pragma unroll
        for (int k = 0; k < HID; k++) {
            za = fmaf(hk[k], wa[k], za);
            zb = fmaf(hk[k], wb[k], zb);
        }
        za = fmaxf(za, 0.0f);
        zb = fmaxf(zb, 0.0f);
        float sacc = za * W2[lane] + zb * W2[lane + 32];
#pragma unroll
        for (int off = 16; off > 0; off >>= 1)
            sacc += __shfl_xor_sync(FULL, sacc, off);
        if (lane == 0) out[b] = 4.0f * sigx(sacc + b2[0]);
    }
}

// ---------------- launch ----------------
extern "C" void kernel_launch(void* const* d_in, const int* in_sizes, int n_in,
                              void* d_out, int out_size) {
    const float* x    = (const float*)d_in[0];
    const float* W_ih = (const float*)d_in[1];
    const float* W_hh = (const float*)d_in[2];
    const float* b_ih = (const float*)d_in[3];
    const float* b_hh = (const float*)d_in[4];
    const float* W1   = (const float*)d_in[5];
    const float* b1   = (const float*)d_in[6];
    const float* W2   = (const float*)d_in[7];
    const float* b2   = (const float*)d_in[8];
    float* out = (float*)d_out;

    cudaFuncSetAttribute(fused_kernel, cudaFuncAttributeMaxDynamicSharedMemorySize, SMEM_BYTES);
    zero_flags<<<16, 256>>>();
    fused_kernel<<<GEMM_BLKS + SCAN_BLKS, 128, SMEM_BYTES>>>(x, W_ih, W_hh, b_ih, b_hh,
                                                             W1, b1, W2, b2, out);
}

// round 15
// speedup vs baseline: 1.3354x; 1.3354x over previous
#include <cuda_runtime.h>
#include <cuda_bf16.h>
#include <cstdint>

#define T_STEPS 512
#define BATCH   512
#define INSZ    300
#define HID     16
#define NG      64
#define NROWS   (T_STEPS*BATCH)     // 262144
#define TILE_M  128
#define NTILES  (NROWS/TILE_M)      // 2048
#define GRID_G  296                 // 2 blocks per SM
#define NPARTS  4
#define TILES_PER_PART (NTILES/NPARTS)   // 512
#define T_PER_PART (T_STEPS/NPARTS)      // 128
#define STRIDE_T (BATCH*NG)
#define ASTRIDE 72

#define A_ELEMS (TILE_M*ASTRIDE)    // 9216 floats per buffer
#define B_WORDS (19*64*8)           // 9728 uint32
#define SMEM_BYTES (2*A_ELEMS*4 + B_WORDS*4)   // 112640

__device__ float d_xg[(size_t)(NROWS + 8 * BATCH) * NG];
__device__ float d_hs[BATCH * HID];
__device__ float d_cs[BATCH * HID];

// ---------------- asm helpers ----------------
__device__ __forceinline__ uint32_t smem_u32(const void* p) {
    uint32_t a;
    asm("{ .reg .u64 t; cvta.to.shared.u64 t, %1; cvt.u32.u64 %0, t; }" : "=r"(a) : "l"(p));
    return a;
}
__device__ __forceinline__ void cp16(uint32_t sa, const float* g) {
    asm volatile("cp.async.cg.shared.global [%0], [%1], 16;" :: "r"(sa), "l"(g) : "memory");
}
#define CP_COMMIT() asm volatile("cp.async.commit_group;" ::: "memory")
#define CP_WAIT1()  asm volatile("cp.async.wait_group 1;" ::: "memory")

__device__ __forceinline__ void mma16816(float* d, uint32_t a0, uint32_t a1, uint32_t a2,
                                         uint32_t a3, uint32_t b0, uint32_t b1) {
    asm volatile(
        "mma.sync.aligned.m16n8k16.row.col.f32.bf16.bf16.f32 "
        "{%0,%1,%2,%3}, {%4,%5,%6,%7}, {%8,%9}, {%0,%1,%2,%3};"
        : "+f"(d[0]), "+f"(d[1]), "+f"(d[2]), "+f"(d[3])
        : "r"(a0), "r"(a1), "r"(a2), "r"(a3), "r"(b0), "r"(b1));
}
__device__ __forceinline__ uint32_t packbf(float lo, float hi) {
    __nv_bfloat162 p = __floats2bfloat162_rn(lo, hi);
    return *reinterpret_cast<uint32_t*>(&p);
}
__device__ __forceinline__ float tanhapx(float x) {
    float y;
    asm("tanh.approx.f32 %0, %1;" : "=f"(y) : "f"(x));
    return y;
}
__device__ __forceinline__ float sigt(float x) {
    return fmaf(tanhapx(0.5f * x), 0.5f, 0.5f);
}
__device__ __forceinline__ float sigx(float x) {
    float e = __expf(-x);
    return __fdividef(1.0f, 1.0f + e);
}

// copy one 64-col K-chunk of a 128-row tile (256 threads)
__device__ __forceinline__ void cp_chunk(const float* __restrict__ x, uint32_t abase,
                                         int tile, int ch) {
    const int tid = threadIdx.x;
    const int j  = tid & 15;
    const int rr = tid >> 4;          // 0..15
    const int c0 = ch * 64;
    const int jmax = (ch == 4) ? 11 : 16;
#pragma unroll
    for (int p = 0; p < 8; p++) {
        int r = p * 16 + rr;
        uint32_t soff = abase + ((uint32_t)(r * ASTRIDE) + 4u * (uint32_t)j) * 4u;
        if (j < jmax) {
            cp16(soff, x + (size_t)(tile * TILE_M + r) * INSZ + c0 + 4 * j);
        } else if (ch == 4 && j == 11) {
            asm volatile("st.shared.v4.u32 [%0], {%1,%1,%1,%1};" :: "r"(soff), "r"(0u) : "memory");
        }
    }
    CP_COMMIT();
}

// ---------------- GEMM part: tiles [part*512, part*512+512) ----------------
__global__ void __launch_bounds__(256, 2)
gemm_kernel(const float* __restrict__ x, const float* __restrict__ W, int part) {
    extern __shared__ float sm[];
    float* sA0 = sm;
    float* sA1 = sm + A_ELEMS;
    uint32_t* sB = reinterpret_cast<uint32_t*>(sm + 2 * A_ELEMS);
    const uint32_t sbase = smem_u32(sm);
    const uint32_t aB[2] = { sbase, sbase + A_ELEMS * 4u };
    float* sAp[2] = { sA0, sA1 };

    const int tid  = threadIdx.x;
    const int w    = tid >> 5;
    const int lane = tid & 31;
    const int g    = lane >> 2;
    const int tg   = lane & 3;

    const int tbeg = part * TILES_PER_PART;
    const int tend = tbeg + TILES_PER_PART;

    cp_chunk(x, aB[0], tbeg + blockIdx.x, 0);

    // B fill (once per part): W[n][k] fp32 -> bf16x2 fragment-pair layout
    for (int i = tid; i < 19 * 64 * 4; i += 256) {
        int s = i >> 8;
        int n = (i >> 2) & 63;
        int t = i & 3;
        int k0 = 16 * s + 2 * t;
        const float* Wn = W + (size_t)n * INSZ;
        float v0 = (k0     < INSZ) ? Wn[k0]     : 0.0f;
        float v1 = (k0 + 1 < INSZ) ? Wn[k0 + 1] : 0.0f;
        float v2 = (k0 + 8 < INSZ) ? Wn[k0 + 8] : 0.0f;
        float v3 = (k0 + 9 < INSZ) ? Wn[k0 + 9] : 0.0f;
        int base = ((s * 64 + n) * 4 + t) * 2;
        sB[base]     = packbf(v0, v1);
        sB[base + 1] = packbf(v2, v3);
    }
    __syncthreads();

    int buf = 0;
    for (int tile = tbeg + blockIdx.x; tile < tend; tile += GRID_G) {
        float acc[8][4];
#pragma unroll
        for (int j = 0; j < 8; j++)
#pragma unroll
            for (int r = 0; r < 4; r++) acc[j][r] = 0.0f;

        for (int ch = 0; ch < 5; ch++) {
            int ntile = tile, nch = ch + 1;
            if (nch == 5) { ntile = tile + GRID_G; nch = 0; }
            if (ntile < tend) cp_chunk(x, aB[buf ^ 1], ntile, nch);
            else CP_COMMIT();
            CP_WAIT1();
            __syncthreads();

            const float* A = sAp[buf];
            const int nsl = (ch == 4) ? 3 : 4;
            for (int sl = 0; sl < nsl; sl++) {
                const int s = ch * 4 + sl;
                uint2 bb[8];
                const uint2* Bf = reinterpret_cast<const uint2*>(sB)
                                + ((s * 64 + g) * 4 + tg);
#pragma unroll
                for (int j = 0; j < 8; j++) bb[j] = Bf[j * 32];

                const int r0 = w * 16 + g;
                const float* Ab = A + r0 * ASTRIDE + sl * 16 + 2 * tg;
                float2 f0 = *reinterpret_cast<const float2*>(Ab);
                float2 f1 = *reinterpret_cast<const float2*>(Ab + 8 * ASTRIDE);
                float2 f2 = *reinterpret_cast<const float2*>(Ab + 8);
                float2 f3 = *reinterpret_cast<const float2*>(Ab + 8 * ASTRIDE + 8);
                uint32_t a0 = packbf(f0.x, f0.y);
                uint32_t a1 = packbf(f1.x, f1.y);
                uint32_t a2 = packbf(f2.x, f2.y);
                uint32_t a3 = packbf(f3.x, f3.y);
#pragma unroll
                for (int j = 0; j < 8; j++)
                    mma16816(acc[j], a0, a1, a2, a3, bb[j].x, bb[j].y);
            }
            __syncthreads();
            buf ^= 1;
        }

        {
            int r0 = tile * TILE_M + w * 16 + g;
#pragma unroll
            for (int j = 0; j < 8; j++) {
                int col = j * 8 + tg * 2;
                *reinterpret_cast<float2*>(&d_xg[(size_t)r0 * NG + col]) =
                    make_float2(acc[j][0], acc[j][1]);
                *reinterpret_cast<float2*>(&d_xg[(size_t)(r0 + 8) * NG + col]) =
                    make_float2(acc[j][2], acc[j][3]);
            }
        }
    }
}

// ---------------- scan part: 128 steps, state carried in d_hs/d_cs ----------------
__global__ void __launch_bounds__(128, 1)
scan_kernel(int part,
            const float* __restrict__ Whh,
            const float* __restrict__ b_ih, const float* __restrict__ b_hh,
            const float* __restrict__ W1, const float* __restrict__ b1,
            const float* __restrict__ W2, const float* __restrict__ b2,
            float* __restrict__ out) {
    const int warp = threadIdx.x >> 5;
    const int lane = threadIdx.x & 31;
    const int b = blockIdx.x * 4 + warp;
    const int l = lane & 15;
    const unsigned FULL = 0xffffffffu;

    float w1r[HID], w2r[HID];
#pragma unroll
    for (int k = 0; k < HID; k++) {
        w1r[k] = Whh[lane * HID + k];
        w2r[k] = Whh[(lane + 32) * HID + k];
    }
    const float biasA = b_ih[lane] + b_hh[lane];
    const float biasB = b_ih[lane + 32] + b_hh[lane + 32];

    float h, c;
    if (part == 0) {
        h = 0.0f; c = 0.0f;
    } else {
        h = d_hs[b * HID + l];
        c = d_cs[b * HID + l];
    }

    const int t0 = part * T_PER_PART;
    const float* xpA = d_xg + ((size_t)t0 * BATCH + b) * NG + lane;
    const float* xpB = xpA + 32;

    float xa0 = xpA[0 * STRIDE_T], xb0 = xpB[0 * STRIDE_T];
    float xa1 = xpA[1 * STRIDE_T], xb1 = xpB[1 * STRIDE_T];
    float xa2 = xpA[2 * STRIDE_T], xb2 = xpB[2 * STRIDE_T];
    float xa3 = xpA[3 * STRIDE_T], xb3 = xpB[3 * STRIDE_T];

#define STEP(XA, XB, PIDX)                                              \
    {                                                                   \
        float g1 = XA + biasA;                                          \
        float g2 = XB + biasB;                                          \
        XA = xpA[(size_t)(PIDX) * STRIDE_T];                            \
        XB = xpB[(size_t)(PIDX) * STRIDE_T];                            \
        float hk[HID];                                                  \
        _Pragma("unroll")                                               \
        for (int k = 0; k < HID; k++) hk[k] = __shfl_sync(FULL, h, k);  \
        float s0 = g1, s1 = 0.0f, s2 = 0.0f, s3 = 0.0f;                 \
        float r0 = g2, r1 = 0.0f, r2 = 0.0f, r3 = 0.0f;                 \
        _Pragma("unroll")                                               \
        for (int k = 0; k < HID; k += 4) {                              \
            s0 = fmaf(hk[k],     w1r[k],     s0);                       \
            s1 = fmaf(hk[k + 1], w1r[k + 1], s1);                       \
            s2 = fmaf(hk[k + 2], w1r[k + 2], s2);                       \
            s3 = fmaf(hk[k + 3], w1r[k + 3], s3);                       \
            r0 = fmaf(hk[k],     w2r[k],     r0);                       \
            r1 = fmaf(hk[k + 1], w2r[k + 1], r1);                       \
            r2 = fmaf(hk[k + 2], w2r[k + 2], r2);                       \
            r3 = fmaf(hk[k + 3], w2r[k + 3], r3);                       \
        }                                                               \
        g1 = (s0 + s1) + (s2 + s3);                                     \
        g2 = (r0 + r1) + (r2 + r3);                                     \
        float fg = __shfl_sync(FULL, g1, l + 16);                       \
        float og = __shfl_sync(FULL, g2, l + 16);                       \
        float i_s = sigt(g1);                                           \
        float f_s = sigt(fg);                                           \
        float g_t = tanhapx(g2);                                        \
        c = fmaf(f_s, c, i_s * g_t);                                    \
        h = sigt(og) * tanhapx(c);                                      \
    }

    for (int t = 0; t < T_PER_PART; t += 4) {
        const int p = t + 4;
        STEP(xa0, xb0, p + 0)
        STEP(xa1, xb1, p + 1)
        STEP(xa2, xb2, p + 2)
        STEP(xa3, xb3, p + 3)
    }
#undef STEP

    if (part < NPARTS - 1) {
        if (lane < 16) {
            d_hs[b * HID + lane] = h;
            d_cs[b * HID + lane] = c;
        }
        return;
    }

    // ---- fused MLP head (final part) ----
    float hk[HID];
#pragma unroll
    for (int k = 0; k < HID; k++) hk[k] = __shfl_sync(FULL, h, k);

    float wa[HID], wb[HID];
#pragma unroll
    for (int k = 0; k < HID; k++) {
        wa[k] = W1[lane * HID + k];
        wb[k] = W1[(lane + 32) * HID + k];
    }
    float za = b1[lane], zb = b1[lane + 32];
#pragma unroll
    for (int k = 0; k < HID; k++) {
        za = fmaf(hk[k], wa[k], za);
        zb = fmaf(hk[k], wb[k], zb);
    }
    za = fmaxf(za, 0.0f);
    zb = fmaxf(zb, 0.0f);
    float sacc = za * W2[lane] + zb * W2[lane + 32];
#pragma unroll
    for (int off = 16; off > 0; off >>= 1)
        sacc += __shfl_xor_sync(FULL, sacc, off);
    if (lane == 0) out[b] = 4.0f * sigx(sacc + b2[0]);
}

// ---------------- launch: two streams, event-chained software pipeline ----------------
extern "C" void kernel_launch(void* const* d_in, const int* in_sizes, int n_in,
                              void* d_out, int out_size) {
    const float* x    = (const float*)d_in[0];
    const float* W_ih = (const float*)d_in[1];
    const float* W_hh = (const float*)d_in[2];
    const float* b_ih = (const float*)d_in[3];
    const float* b_hh = (const float*)d_in[4];
    const float* W1   = (const float*)d_in[5];
    const float* b1   = (const float*)d_in[6];
    const float* W2   = (const float*)d_in[7];
    const float* b2   = (const float*)d_in[8];
    float* out = (float*)d_out;

    cudaFuncSetAttribute(gemm_kernel, cudaFuncAttributeMaxDynamicSharedMemorySize, SMEM_BYTES);

    // create per-call (kernel_launch runs only during correctness + capture; few calls, no frees needed)
    cudaStream_t s1;
    cudaStreamCreateWithFlags(&s1, cudaStreamNonBlocking);
    cudaEvent_t efork, ejoin, eg[NPARTS];
    cudaEventCreateWithFlags(&efork, cudaEventDisableTiming);
    cudaEventCreateWithFlags(&ejoin, cudaEventDisableTiming);
    for (int p = 0; p < NPARTS; p++)
        cudaEventCreateWithFlags(&eg[p], cudaEventDisableTiming);

    cudaEventRecord(efork, 0);
    cudaStreamWaitEvent(s1, efork, 0);     // fork s1 from the capture (legacy) stream

    for (int p = 0; p < NPARTS; p++) {
        gemm_kernel<<<GRID_G, 256, SMEM_BYTES, 0>>>(x, W_ih, p);
        cudaEventRecord(eg[p], 0);
        cudaStreamWaitEvent(s1, eg[p], 0); // scan part p needs gemm part p
        scan_kernel<<<128, 128, 0, s1>>>(p, W_hh, b_ih, b_hh, W1, b1, W2, b2, out);
    }

    cudaEventRecord(ejoin, s1);
    cudaStreamWaitEvent(0, ejoin, 0);      // join back into the capture stream
}

// round 16
// speedup vs baseline: 1.3383x; 1.0022x over previous
#include <cuda_runtime.h>
#include <cuda_bf16.h>
#include <cstdint>

#define T_STEPS 512
#define BATCH   512
#define INSZ    300
#define HID     16
#define NG      64
#define NROWS   (T_STEPS*BATCH)     // 262144
#define TILE_M  128
#define NTILES  (NROWS/TILE_M)      // 2048
#define GRID_G  296                 // 2 blocks per SM
#define NPARTS  4
#define TILES_PER_PART (NTILES/NPARTS)   // 512
#define T_PER_PART (T_STEPS/NPARTS)      // 128
#define STRIDE_T (BATCH*NG)
#define ASTRIDE 72

#define A_ELEMS (TILE_M*ASTRIDE)    // 9216 floats per buffer
#define B_WORDS (19*64*8)           // 9728 uint32
#define SMEM_BYTES (2*A_ELEMS*4 + B_WORDS*4)   // 112640

__device__ float d_xg[(size_t)(NROWS + 8 * BATCH) * NG];
__device__ float d_hs[BATCH * HID];
__device__ float d_cs[BATCH * HID];

// ---------------- asm helpers ----------------
__device__ __forceinline__ uint32_t smem_u32(const void* p) {
    uint32_t a;
    asm("{ .reg .u64 t; cvta.to.shared.u64 t, %1; cvt.u32.u64 %0, t; }" : "=r"(a) : "l"(p));
    return a;
}
__device__ __forceinline__ void cp16(uint32_t sa, const float* g) {
    asm volatile("cp.async.cg.shared.global [%0], [%1], 16;" :: "r"(sa), "l"(g) : "memory");
}
#define CP_COMMIT() asm volatile("cp.async.commit_group;" ::: "memory")
#define CP_WAIT1()  asm volatile("cp.async.wait_group 1;" ::: "memory")

__device__ __forceinline__ void mma16816(float* d, uint32_t a0, uint32_t a1, uint32_t a2,
                                         uint32_t a3, uint32_t b0, uint32_t b1) {
    asm volatile(
        "mma.sync.aligned.m16n8k16.row.col.f32.bf16.bf16.f32 "
        "{%0,%1,%2,%3}, {%4,%5,%6,%7}, {%8,%9}, {%0,%1,%2,%3};"
        : "+f"(d[0]), "+f"(d[1]), "+f"(d[2]), "+f"(d[3])
        : "r"(a0), "r"(a1), "r"(a2), "r"(a3), "r"(b0), "r"(b1));
}
__device__ __forceinline__ uint32_t packbf(float lo, float hi) {
    __nv_bfloat162 p = __floats2bfloat162_rn(lo, hi);
    return *reinterpret_cast<uint32_t*>(&p);
}
__device__ __forceinline__ float tanhapx(float x) {
    float y;
    asm("tanh.approx.f32 %0, %1;" : "=f"(y) : "f"(x));
    return y;
}
__device__ __forceinline__ float sigt(float x) {
    return fmaf(tanhapx(0.5f * x), 0.5f, 0.5f);
}
__device__ __forceinline__ float sigx(float x) {
    float e = __expf(-x);
    return __fdividef(1.0f, 1.0f + e);
}

// copy one 64-col K-chunk of a 128-row tile (256 threads)
__device__ __forceinline__ void cp_chunk(const float* __restrict__ x, uint32_t abase,
                                         int tile, int ch) {
    const int tid = threadIdx.x;
    const int j  = tid & 15;
    const int rr = tid >> 4;          // 0..15
    const int c0 = ch * 64;
    const int jmax = (ch == 4) ? 11 : 16;
#pragma unroll
    for (int p = 0; p < 8; p++) {
        int r = p * 16 + rr;
        uint32_t soff = abase + ((uint32_t)(r * ASTRIDE) + 4u * (uint32_t)j) * 4u;
        if (j < jmax) {
            cp16(soff, x + (size_t)(tile * TILE_M + r) * INSZ + c0 + 4 * j);
        } else if (ch == 4 && j == 11) {
            asm volatile("st.shared.v4.u32 [%0], {%1,%1,%1,%1};" :: "r"(soff), "r"(0u) : "memory");
        }
    }
    CP_COMMIT();
}

// ---------------- GEMM part: tiles [part*512, part*512+512) ----------------
__global__ void __launch_bounds__(256, 2)
gemm_kernel(const float* __restrict__ x, const float* __restrict__ W, int part) {
    extern __shared__ float sm[];
    float* sA0 = sm;
    float* sA1 = sm + A_ELEMS;
    uint32_t* sB = reinterpret_cast<uint32_t*>(sm + 2 * A_ELEMS);
    const uint32_t sbase = smem_u32(sm);
    const uint32_t aB[2] = { sbase, sbase + A_ELEMS * 4u };
    float* sAp[2] = { sA0, sA1 };

    const int tid  = threadIdx.x;
    const int w    = tid >> 5;
    const int lane = tid & 31;
    const int g    = lane >> 2;
    const int tg   = lane & 3;

    const int tbeg = part * TILES_PER_PART;
    const int tend = tbeg + TILES_PER_PART;

    cp_chunk(x, aB[0], tbeg + blockIdx.x, 0);

    // B fill (once per part): W[n][k] fp32 -> bf16x2 fragment-pair layout
    for (int i = tid; i < 19 * 64 * 4; i += 256) {
        int s = i >> 8;
        int n = (i >> 2) & 63;
        int t = i & 3;
        int k0 = 16 * s + 2 * t;
        const float* Wn = W + (size_t)n * INSZ;
        float v0 = (k0     < INSZ) ? Wn[k0]     : 0.0f;
        float v1 = (k0 + 1 < INSZ) ? Wn[k0 + 1] : 0.0f;
        float v2 = (k0 + 8 < INSZ) ? Wn[k0 + 8] : 0.0f;
        float v3 = (k0 + 9 < INSZ) ? Wn[k0 + 9] : 0.0f;
        int base = ((s * 64 + n) * 4 + t) * 2;
        sB[base]     = packbf(v0, v1);
        sB[base + 1] = packbf(v2, v3);
    }
    __syncthreads();

    int buf = 0;
    for (int tile = tbeg + blockIdx.x; tile < tend; tile += GRID_G) {
        float acc[8][4];
#pragma unroll
        for (int j = 0; j < 8; j++)
#pragma unroll
            for (int r = 0; r < 4; r++) acc[j][r] = 0.0f;

        for (int ch = 0; ch < 5; ch++) {
            int ntile = tile, nch = ch + 1;
            if (nch == 5) { ntile = tile + GRID_G; nch = 0; }
            if (ntile < tend) cp_chunk(x, aB[buf ^ 1], ntile, nch);
            else CP_COMMIT();
            CP_WAIT1();
            __syncthreads();

            const float* A = sAp[buf];
            const int nsl = (ch == 4) ? 3 : 4;
            for (int sl = 0; sl < nsl; sl++) {
                const int s = ch * 4 + sl;
                uint2 bb[8];
                const uint2* Bf = reinterpret_cast<const uint2*>(sB)
                                + ((s * 64 + g) * 4 + tg);
#pragma unroll
                for (int j = 0; j < 8; j++) bb[j] = Bf[j * 32];

                const int r0 = w * 16 + g;
                const float* Ab = A + r0 * ASTRIDE + sl * 16 + 2 * tg;
                float2 f0 = *reinterpret_cast<const float2*>(Ab);
                float2 f1 = *reinterpret_cast<const float2*>(Ab + 8 * ASTRIDE);
                float2 f2 = *reinterpret_cast<const float2*>(Ab + 8);
                float2 f3 = *reinterpret_cast<const float2*>(Ab + 8 * ASTRIDE + 8);
                uint32_t a0 = packbf(f0.x, f0.y);
                uint32_t a1 = packbf(f1.x, f1.y);
                uint32_t a2 = packbf(f2.x, f2.y);
                uint32_t a3 = packbf(f3.x, f3.y);
#pragma unroll
                for (int j = 0; j < 8; j++)
                    mma16816(acc[j], a0, a1, a2, a3, bb[j].x, bb[j].y);
            }
            __syncthreads();
            buf ^= 1;
        }

        {
            int r0 = tile * TILE_M + w * 16 + g;
#pragma unroll
            for (int j = 0; j < 8; j++) {
                int col = j * 8 + tg * 2;
                *reinterpret_cast<float2*>(&d_xg[(size_t)r0 * NG + col]) =
                    make_float2(acc[j][0], acc[j][1]);
                *reinterpret_cast<float2*>(&d_xg[(size_t)(r0 + 8) * NG + col]) =
                    make_float2(acc[j][2], acc[j][3]);
            }
        }
    }
}

// ---------------- scan part: 128 steps, state carried in d_hs/d_cs ----------------
__global__ void __launch_bounds__(128, 1)
scan_kernel(int part,
            const float* __restrict__ Whh,
            const float* __restrict__ b_ih, const float* __restrict__ b_hh,
            const float* __restrict__ W1, const float* __restrict__ b1,
            const float* __restrict__ W2, const float* __restrict__ b2,
            float* __restrict__ out) {
    const int warp = threadIdx.x >> 5;
    const int lane = threadIdx.x & 31;
    const int b = blockIdx.x * 4 + warp;
    const int l = lane & 15;
    const unsigned FULL = 0xffffffffu;

    float w1r[HID], w2r[HID];
#pragma unroll
    for (int k = 0; k < HID; k++) {
        w1r[k] = Whh[lane * HID + k];
        w2r[k] = Whh[(lane + 32) * HID + k];
    }
    const float biasA = b_ih[lane] + b_hh[lane];
    const float biasB = b_ih[lane + 32] + b_hh[lane + 32];

    float h, c;
    if (part == 0) {
        h = 0.0f; c = 0.0f;
    } else {
        h = d_hs[b * HID + l];
        c = d_cs[b * HID + l];
    }

    const int t0 = part * T_PER_PART;
    const float* xpA = d_xg + ((size_t)t0 * BATCH + b) * NG + lane;
    const float* xpB = xpA + 32;

    float xa0 = xpA[0 * STRIDE_T], xb0 = xpB[0 * STRIDE_T];
    float xa1 = xpA[1 * STRIDE_T], xb1 = xpB[1 * STRIDE_T];
    float xa2 = xpA[2 * STRIDE_T], xb2 = xpB[2 * STRIDE_T];
    float xa3 = xpA[3 * STRIDE_T], xb3 = xpB[3 * STRIDE_T];

#define STEP(XA, XB, PIDX)                                              \
    {                                                                   \
        float g1 = XA + biasA;                                          \
        float g2 = XB + biasB;                                          \
        XA = xpA[(size_t)(PIDX) * STRIDE_T];                            \
        XB = xpB[(size_t)(PIDX) * STRIDE_T];                            \
        float hk[HID];                                                  \
        _Pragma("unroll")                                               \
        for (int k = 0; k < HID; k++) hk[k] = __shfl_sync(FULL, h, k);  \
        float s0 = g1, s1 = 0.0f, s2 = 0.0f, s3 = 0.0f;                 \
        float r0 = g2, r1 = 0.0f, r2 = 0.0f, r3 = 0.0f;                 \
        _Pragma("unroll")                                               \
        for (int k = 0; k < HID; k += 4) {                              \
            s0 = fmaf(hk[k],     w1r[k],     s0);                       \
            s1 = fmaf(hk[k + 1], w1r[k + 1], s1);                       \
            s2 = fmaf(hk[k + 2], w1r[k + 2], s2);                       \
            s3 = fmaf(hk[k + 3], w1r[k + 3], s3);                       \
            r0 = fmaf(hk[k],     w2r[k],     r0);                       \
            r1 = fmaf(hk[k + 1], w2r[k + 1], r1);                       \
            r2 = fmaf(hk[k + 2], w2r[k + 2], r2);                       \
            r3 = fmaf(hk[k + 3], w2r[k + 3], r3);                       \
        }                                                               \
        g1 = (s0 + s1) + (s2 + s3);                                     \
        g2 = (r0 + r1) + (r2 + r3);                                     \
        float fg = __shfl_sync(FULL, g1, l + 16);                       \
        float og = __shfl_sync(FULL, g2, l + 16);                       \
        float i_s = sigt(g1);                                           \
        float f_s = sigt(fg);                                           \
        float g_t = tanhapx(g2);                                        \
        c = fmaf(f_s, c, i_s * g_t);                                    \
        h = sigt(og) * tanhapx(c);                                      \
    }

    for (int t = 0; t < T_PER_PART; t += 4) {
        const int p = t + 4;
        STEP(xa0, xb0, p + 0)
        STEP(xa1, xb1, p + 1)
        STEP(xa2, xb2, p + 2)
        STEP(xa3, xb3, p + 3)
    }
#undef STEP

    if (part < NPARTS - 1) {
        if (lane < 16) {
            d_hs[b * HID + lane] = h;
            d_cs[b * HID + lane] = c;
        }
        return;
    }

    // ---- fused MLP head (final part) ----
    float hk[HID];
#pragma unroll
    for (int k = 0; k < HID; k++) hk[k] = __shfl_sync(FULL, h, k);

    float wa[HID], wb[HID];
#pragma unroll
    for (int k = 0; k < HID; k++) {
        wa[k] = W1[lane * HID + k];
        wb[k] = W1[(lane + 32) * HID + k];
    }
    float za = b1[lane], zb = b1[lane + 32];
#pragma unroll
    for (int k = 0; k < HID; k++) {
        za = fmaf(hk[k], wa[k], za);
        zb = fmaf(hk[k], wb[k], zb);
    }
    za = fmaxf(za, 0.0f);
    zb = fmaxf(zb, 0.0f);
    float sacc = za * W2[lane] + zb * W2[lane + 32];
#pragma unroll
    for (int off = 16; off > 0; off >>= 1)
        sacc += __shfl_xor_sync(FULL, sacc, off);
    if (lane == 0) out[b] = 4.0f * sigx(sacc + b2[0]);
}

// ---------------- launch: priority scan stream, event-chained pipeline ----------------
extern "C" void kernel_launch(void* const* d_in, const int* in_sizes, int n_in,
                              void* d_out, int out_size) {
    const float* x    = (const float*)d_in[0];
    const float* W_ih = (const float*)d_in[1];
    const float* W_hh = (const float*)d_in[2];
    const float* b_ih = (const float*)d_in[3];
    const float* b_hh = (const float*)d_in[4];
    const float* W1   = (const float*)d_in[5];
    const float* b1   = (const float*)d_in[6];
    const float* W2   = (const float*)d_in[7];
    const float* b2   = (const float*)d_in[8];
    float* out = (float*)d_out;

    static bool inited = false;
    static cudaStream_t s1;
    static cudaEvent_t efork, ejoin, eg[NPARTS];
    if (!inited) {
        cudaFuncSetAttribute(gemm_kernel, cudaFuncAttributeMaxDynamicSharedMemorySize, SMEM_BYTES);
        int lo = 0, hi = 0;
        cudaDeviceGetStreamPriorityRange(&lo, &hi);   // hi = highest priority
        cudaStreamCreateWithPriority(&s1, cudaStreamNonBlocking, hi);
        cudaEventCreateWithFlags(&efork, cudaEventDisableTiming);
        cudaEventCreateWithFlags(&ejoin, cudaEventDisableTiming);
        for (int p = 0; p < NPARTS; p++)
            cudaEventCreateWithFlags(&eg[p], cudaEventDisableTiming);
        inited = true;
    }

    cudaEventRecord(efork, 0);
    cudaStreamWaitEvent(s1, efork, 0);     // fork s1 from the capture (legacy) stream

    for (int p = 0; p < NPARTS; p++) {
        gemm_kernel<<<GRID_G, 256, SMEM_BYTES, 0>>>(x, W_ih, p);
        cudaEventRecord(eg[p], 0);
        cudaStreamWaitEvent(s1, eg[p], 0); // scan part p needs gemm part p
        scan_kernel<<<128, 128, 0, s1>>>(p, W_hh, b_ih, b_hh, W1, b1, W2, b2, out);
    }

    cudaEventRecord(ejoin, s1);
    cudaStreamWaitEvent(0, ejoin, 0);      // join back into the capture stream
}